// round 1
// baseline (speedup 1.0000x reference)
#include <cuda_runtime.h>
#include <math.h>

#define EPS      1e-5f
#define THREADS  256
#define NPTS     (64 * 1024)
#define HSTRIDE  66   // padded row stride (floats): 2-way max bank conflict, 8B aligned

// SMEM layout (float offsets)
#define SM_W1 0                      // 64x32 folded
#define SM_W2 (SM_W1 + 64 * 32)      // 64x64 folded
#define SM_W3 (SM_W2 + 64 * 64)      // 64x64 folded
#define SM_B1 (SM_W3 + 64 * 64)      // 64
#define SM_B2 (SM_B1 + 64)
#define SM_B3 (SM_B2 + 64)
#define SM_H  (SM_B3 + 64)           // 256 rows x HSTRIDE
#define SMEM_FLOATS (SM_H + THREADS * HSTRIDE)
#define SMEM_BYTES  (SMEM_FLOATS * 4)

typedef unsigned long long ull;

// Packed fp32x2 FMA (Blackwell): 2 FMAs per issue slot; ptxas never auto-fuses this.
__device__ __forceinline__ ull fma2(ull a, ull b, ull c) {
    ull d;
    asm("fma.rn.f32x2 %0, %1, %2, %3;" : "=l"(d) : "l"(a), "l"(b), "l"(c));
    return d;
}

__device__ __forceinline__ float sum2(ull a) {
    float x, y;
    asm("mov.b64 {%0, %1}, %2;" : "=f"(x), "=f"(y) : "l"(a));
    return x + y;
}

// Exact GELU: x * Phi(x), matches jax.nn.gelu(approximate=False)
__device__ __forceinline__ float gelu(float v) { return v * normcdff(v); }

__global__ void __launch_bounds__(THREADS, 2) edgeconv_mlp_kernel(
    const float* __restrict__ x,
    const float* __restrict__ W1, const float* __restrict__ g1, const float* __restrict__ b1,
    const float* __restrict__ m1, const float* __restrict__ v1,
    const float* __restrict__ W2, const float* __restrict__ g2, const float* __restrict__ b2,
    const float* __restrict__ m2, const float* __restrict__ v2,
    const float* __restrict__ W3, const float* __restrict__ g3, const float* __restrict__ b3,
    const float* __restrict__ m3, const float* __restrict__ v3,
    float* __restrict__ out)
{
    extern __shared__ float sm[];
    const int tid = threadIdx.x;

    // ---- Fold BN into weights/bias, stage into SMEM (per block; trivially cheap) ----
    for (int i = tid; i < 64 * 32; i += THREADS) {
        int o = i >> 5;
        sm[SM_W1 + i] = W1[i] * (g1[o] * rsqrtf(v1[o] + EPS));
    }
    for (int i = tid; i < 64 * 64; i += THREADS) {
        int o = i >> 6;
        sm[SM_W2 + i] = W2[i] * (g2[o] * rsqrtf(v2[o] + EPS));
        sm[SM_W3 + i] = W3[i] * (g3[o] * rsqrtf(v3[o] + EPS));
    }
    if (tid < 64) {
        float s1 = g1[tid] * rsqrtf(v1[tid] + EPS);
        float s2 = g2[tid] * rsqrtf(v2[tid] + EPS);
        float s3 = g3[tid] * rsqrtf(v3[tid] + EPS);
        sm[SM_B1 + tid] = b1[tid] - m1[tid] * s1;
        sm[SM_B2 + tid] = b2[tid] - m2[tid] * s2;
        sm[SM_B3 + tid] = b3[tid] - m3[tid] * s3;
    }
    __syncthreads();

    // ---- Per-point 3-stage MLP (neighbor gather in the reference is identity; top_k dead) ----
    const int p = blockIdx.x * THREADS + tid;     // 0..65535
    const int bidx = p >> 10;
    const int n    = p & 1023;
    float* hrow = sm + SM_H + tid * HSTRIDE;      // private row: no cross-thread sharing, no syncs

    // Load x[p, 0:32] as 16 pre-packed f32x2 pairs (128B-aligned)
    ull xp[16];
    {
        const ulonglong2* xg = (const ulonglong2*)(x + (size_t)p * 32);
        #pragma unroll
        for (int i = 0; i < 8; ++i) { ulonglong2 v = xg[i]; xp[2 * i] = v.x; xp[2 * i + 1] = v.y; }
    }

    // Stage 1: 32 -> 64
    #pragma unroll 2
    for (int o = 0; o < 64; ++o) {
        const ulonglong2* wr = (const ulonglong2*)(sm + SM_W1 + o * 32);
        ull a0 = 0ULL, a1 = 0ULL;
        #pragma unroll
        for (int q = 0; q < 8; ++q) {
            ulonglong2 w = wr[q];                 // broadcast LDS.128: 2 packed pairs
            a0 = fma2(w.x, xp[2 * q],     a0);
            a1 = fma2(w.y, xp[2 * q + 1], a1);
        }
        hrow[o] = gelu(sum2(a0) + sum2(a1) + sm[SM_B1 + o]);
    }

    ull hp[32];
    #pragma unroll
    for (int q = 0; q < 32; ++q) hp[q] = *(const ull*)(hrow + 2 * q);

    // Stage 2: 64 -> 64
    #pragma unroll 2
    for (int o = 0; o < 64; ++o) {
        const ulonglong2* wr = (const ulonglong2*)(sm + SM_W2 + o * 64);
        ull a0 = 0ULL, a1 = 0ULL;
        #pragma unroll
        for (int q = 0; q < 16; ++q) {
            ulonglong2 w = wr[q];
            a0 = fma2(w.x, hp[2 * q],     a0);
            a1 = fma2(w.y, hp[2 * q + 1], a1);
        }
        hrow[o] = gelu(sum2(a0) + sum2(a1) + sm[SM_B2 + o]);
    }

    #pragma unroll
    for (int q = 0; q < 32; ++q) hp[q] = *(const ull*)(hrow + 2 * q);

    // Stage 3: 64 -> 64, store transposed out[b, o, n] (coalesced per warp: n contiguous)
    float* outp = out + ((size_t)bidx * 64) * 1024 + n;
    #pragma unroll 2
    for (int o = 0; o < 64; ++o) {
        const ulonglong2* wr = (const ulonglong2*)(sm + SM_W3 + o * 64);
        ull a0 = 0ULL, a1 = 0ULL;
        #pragma unroll
        for (int q = 0; q < 16; ++q) {
            ulonglong2 w = wr[q];
            a0 = fma2(w.x, hp[2 * q],     a0);
            a1 = fma2(w.y, hp[2 * q + 1], a1);
        }
        outp[(size_t)o * 1024] = gelu(sum2(a0) + sum2(a1) + sm[SM_B3 + o]);
    }
}

extern "C" void kernel_launch(void* const* d_in, const int* in_sizes, int n_in,
                              void* d_out, int out_size)
{
    const float* x  = (const float*)d_in[0];
    const float* W1 = (const float*)d_in[1];
    const float* g1 = (const float*)d_in[2];
    const float* b1 = (const float*)d_in[3];
    const float* m1 = (const float*)d_in[4];
    const float* v1 = (const float*)d_in[5];
    const float* W2 = (const float*)d_in[6];
    const float* g2 = (const float*)d_in[7];
    const float* b2 = (const float*)d_in[8];
    const float* m2 = (const float*)d_in[9];
    const float* v2 = (const float*)d_in[10];
    const float* W3 = (const float*)d_in[11];
    const float* g3 = (const float*)d_in[12];
    const float* b3 = (const float*)d_in[13];
    const float* m3 = (const float*)d_in[14];
    const float* v3 = (const float*)d_in[15];
    float* out = (float*)d_out;

    cudaFuncSetAttribute(edgeconv_mlp_kernel,
                         cudaFuncAttributeMaxDynamicSharedMemorySize, SMEM_BYTES);

    edgeconv_mlp_kernel<<<NPTS / THREADS, THREADS, SMEM_BYTES>>>(
        x, W1, g1, b1, m1, v1, W2, g2, b2, m2, v2, W3, g3, b3, m3, v3, out);
}

// round 2
// speedup vs baseline: 1.1878x; 1.1878x over previous
#include <cuda_runtime.h>
#include <math.h>

#define EPS      1e-5f
#define THREADS  256
#define NPTS     (64 * 1024)
#define HSTRIDE  66   // padded row stride (floats): 2-way max bank conflict, 8B aligned

// SMEM layout (float offsets)
#define SM_W1 0                      // 64x32 folded
#define SM_W2 (SM_W1 + 64 * 32)      // 64x64 folded
#define SM_W3 (SM_W2 + 64 * 64)      // 64x64 folded
#define SM_B1 (SM_W3 + 64 * 64)      // 64
#define SM_B2 (SM_B1 + 64)
#define SM_B3 (SM_B2 + 64)
#define SM_H  (SM_B3 + 64)           // 256 rows x HSTRIDE
#define SMEM_FLOATS (SM_H + THREADS * HSTRIDE)
#define SMEM_BYTES  (SMEM_FLOATS * 4)

typedef unsigned long long ull;

// Packed fp32x2 FMA (Blackwell): 2 FMAs per issue slot; ptxas never auto-fuses this.
__device__ __forceinline__ ull fma2(ull a, ull b, ull c) {
    ull d;
    asm("fma.rn.f32x2 %0, %1, %2, %3;" : "=l"(d) : "l"(a), "l"(b), "l"(c));
    return d;
}

__device__ __forceinline__ ull add2(ull a, ull b) {
    ull d;
    asm("add.rn.f32x2 %0, %1, %2;" : "=l"(d) : "l"(a), "l"(b));
    return d;
}

__device__ __forceinline__ float sum2(ull a) {
    float x, y;
    asm("mov.b64 {%0, %1}, %2;" : "=f"(x), "=f"(y) : "l"(a));
    return x + y;
}

// Exact GELU: x * Phi(x) = 0.5*x*(1 + erf(x/sqrt(2))).
// erff is a short branch-free polynomial; normcdff routes through erfcf which
// is far more expensive (branchy rational approx). Same math, same accuracy class.
__device__ __forceinline__ float gelu(float v) {
    float e = erff(v * 0.70710678118654752f);
    float h = 0.5f * v;
    return fmaf(h, e, h);
}

__global__ void __launch_bounds__(THREADS, 2) edgeconv_mlp_kernel(
    const float* __restrict__ x,
    const float* __restrict__ W1, const float* __restrict__ g1, const float* __restrict__ b1,
    const float* __restrict__ m1, const float* __restrict__ v1,
    const float* __restrict__ W2, const float* __restrict__ g2, const float* __restrict__ b2,
    const float* __restrict__ m2, const float* __restrict__ v2,
    const float* __restrict__ W3, const float* __restrict__ g3, const float* __restrict__ b3,
    const float* __restrict__ m3, const float* __restrict__ v3,
    float* __restrict__ out)
{
    extern __shared__ float sm[];
    const int tid = threadIdx.x;

    // ---- Fold BN into weights/bias, stage into SMEM (per block; one-time) ----
    for (int i = tid; i < 64 * 32; i += THREADS) {
        int o = i >> 5;
        sm[SM_W1 + i] = W1[i] * (g1[o] * rsqrtf(v1[o] + EPS));
    }
    for (int i = tid; i < 64 * 64; i += THREADS) {
        int o = i >> 6;
        sm[SM_W2 + i] = W2[i] * (g2[o] * rsqrtf(v2[o] + EPS));
        sm[SM_W3 + i] = W3[i] * (g3[o] * rsqrtf(v3[o] + EPS));
    }
    if (tid < 64) {
        float s1 = g1[tid] * rsqrtf(v1[tid] + EPS);
        float s2 = g2[tid] * rsqrtf(v2[tid] + EPS);
        float s3 = g3[tid] * rsqrtf(v3[tid] + EPS);
        sm[SM_B1 + tid] = b1[tid] - m1[tid] * s1;
        sm[SM_B2 + tid] = b2[tid] - m2[tid] * s2;
        sm[SM_B3 + tid] = b3[tid] - m3[tid] * s3;
    }
    __syncthreads();

    // ---- Per-point 3-stage MLP (neighbor gather in the reference is identity; top_k dead) ----
    const int p = blockIdx.x * THREADS + tid;     // 0..65535
    const int bidx = p >> 10;
    const int n    = p & 1023;
    float* hrow = sm + SM_H + tid * HSTRIDE;      // private row: no cross-thread sharing, no syncs

    // Load x[p, 0:32] as 16 pre-packed f32x2 pairs (128B-aligned)
    ull xp[16];
    {
        const ulonglong2* xg = (const ulonglong2*)(x + (size_t)p * 32);
        #pragma unroll
        for (int i = 0; i < 8; ++i) { ulonglong2 v = xg[i]; xp[2 * i] = v.x; xp[2 * i + 1] = v.y; }
    }

    // Stage 1: 32 -> 64  (4 independent accumulator chains, 4-deep each)
    #pragma unroll 2
    for (int o = 0; o < 64; ++o) {
        const ulonglong2* wr = (const ulonglong2*)(sm + SM_W1 + o * 32);
        ull a0 = 0ULL, a1 = 0ULL, a2 = 0ULL, a3 = 0ULL;
        #pragma unroll
        for (int q = 0; q < 8; q += 2) {
            ulonglong2 wa = wr[q];
            ulonglong2 wb = wr[q + 1];
            a0 = fma2(wa.x, xp[2 * q],     a0);
            a1 = fma2(wa.y, xp[2 * q + 1], a1);
            a2 = fma2(wb.x, xp[2 * q + 2], a2);
            a3 = fma2(wb.y, xp[2 * q + 3], a3);
        }
        ull s = add2(add2(a0, a1), add2(a2, a3));
        hrow[o] = gelu(sum2(s) + sm[SM_B1 + o]);
    }

    ull hp[32];
    #pragma unroll
    for (int q = 0; q < 32; ++q) hp[q] = *(const ull*)(hrow + 2 * q);

    // Stage 2: 64 -> 64  (4 chains, 8-deep each)
    #pragma unroll 2
    for (int o = 0; o < 64; ++o) {
        const ulonglong2* wr = (const ulonglong2*)(sm + SM_W2 + o * 64);
        ull a0 = 0ULL, a1 = 0ULL, a2 = 0ULL, a3 = 0ULL;
        #pragma unroll
        for (int q = 0; q < 16; q += 2) {
            ulonglong2 wa = wr[q];
            ulonglong2 wb = wr[q + 1];
            a0 = fma2(wa.x, hp[2 * q],     a0);
            a1 = fma2(wa.y, hp[2 * q + 1], a1);
            a2 = fma2(wb.x, hp[2 * q + 2], a2);
            a3 = fma2(wb.y, hp[2 * q + 3], a3);
        }
        ull s = add2(add2(a0, a1), add2(a2, a3));
        hrow[o] = gelu(sum2(s) + sm[SM_B2 + o]);
    }

    #pragma unroll
    for (int q = 0; q < 32; ++q) hp[q] = *(const ull*)(hrow + 2 * q);

    // Stage 3: 64 -> 64, store transposed out[b, o, n] (coalesced per warp: n contiguous)
    float* outp = out + ((size_t)bidx * 64) * 1024 + n;
    #pragma unroll 2
    for (int o = 0; o < 64; ++o) {
        const ulonglong2* wr = (const ulonglong2*)(sm + SM_W3 + o * 64);
        ull a0 = 0ULL, a1 = 0ULL, a2 = 0ULL, a3 = 0ULL;
        #pragma unroll
        for (int q = 0; q < 16; q += 2) {
            ulonglong2 wa = wr[q];
            ulonglong2 wb = wr[q + 1];
            a0 = fma2(wa.x, hp[2 * q],     a0);
            a1 = fma2(wa.y, hp[2 * q + 1], a1);
            a2 = fma2(wb.x, hp[2 * q + 2], a2);
            a3 = fma2(wb.y, hp[2 * q + 3], a3);
        }
        ull s = add2(add2(a0, a1), add2(a2, a3));
        outp[(size_t)o * 1024] = gelu(sum2(s) + sm[SM_B3 + o]);
    }
}

extern "C" void kernel_launch(void* const* d_in, const int* in_sizes, int n_in,
                              void* d_out, int out_size)
{
    const float* x  = (const float*)d_in[0];
    const float* W1 = (const float*)d_in[1];
    const float* g1 = (const float*)d_in[2];
    const float* b1 = (const float*)d_in[3];
    const float* m1 = (const float*)d_in[4];
    const float* v1 = (const float*)d_in[5];
    const float* W2 = (const float*)d_in[6];
    const float* g2 = (const float*)d_in[7];
    const float* b2 = (const float*)d_in[8];
    const float* m2 = (const float*)d_in[9];
    const float* v2 = (const float*)d_in[10];
    const float* W3 = (const float*)d_in[11];
    const float* g3 = (const float*)d_in[12];
    const float* b3 = (const float*)d_in[13];
    const float* m3 = (const float*)d_in[14];
    const float* v3 = (const float*)d_in[15];
    float* out = (float*)d_out;

    cudaFuncSetAttribute(edgeconv_mlp_kernel,
                         cudaFuncAttributeMaxDynamicSharedMemorySize, SMEM_BYTES);

    edgeconv_mlp_kernel<<<NPTS / THREADS, THREADS, SMEM_BYTES>>>(
        x, W1, g1, b1, m1, v1, W2, g2, b2, m2, v2, W3, g3, b3, m3, v3, out);
}

// round 3
// speedup vs baseline: 1.2004x; 1.0106x over previous
#include <cuda_runtime.h>

#define EPS     1e-5f
#define THREADS 128
#define NPTS    (64 * 1024)

// SMEM layout (float offsets) — folded weights + biases only; no staging.
#define SM_W1 0                      // 64x32
#define SM_W2 (SM_W1 + 64 * 32)      // 64x64
#define SM_W3 (SM_W2 + 64 * 64)      // 64x64
#define SM_B1 (SM_W3 + 64 * 64)
#define SM_B2 (SM_B1 + 64)
#define SM_B3 (SM_B2 + 64)
#define SM_TOT (SM_B3 + 64)          // 10432 floats = 41728 B (static, <48KB)

typedef unsigned long long ull;

__device__ __forceinline__ ull fma2(ull a, ull b, ull c) {
    ull d; asm("fma.rn.f32x2 %0,%1,%2,%3;" : "=l"(d) : "l"(a), "l"(b), "l"(c)); return d;
}
__device__ __forceinline__ ull add2(ull a, ull b) {
    ull d; asm("add.rn.f32x2 %0,%1,%2;" : "=l"(d) : "l"(a), "l"(b)); return d;
}
__device__ __forceinline__ ull mul2(ull a, ull b) {
    ull d; asm("mul.rn.f32x2 %0,%1,%2;" : "=l"(d) : "l"(a), "l"(b)); return d;
}
__device__ __forceinline__ float sum2(ull a) {
    float x, y; asm("mov.b64 {%0,%1}, %2;" : "=f"(x), "=f"(y) : "l"(a)); return x + y;
}
__device__ __forceinline__ void unpk(ull v, float& lo, float& hi) {
    asm("mov.b64 {%0,%1}, %2;" : "=f"(lo), "=f"(hi) : "l"(v));
}
__device__ __forceinline__ ull pk2(float lo, float hi) {
    ull v; asm("mov.b64 %0, {%1,%2};" : "=l"(v) : "f"(lo), "f"(hi)); return v;
}
__device__ __forceinline__ ull pkc(float c) {          // duplicate const into both lanes
    unsigned int u = __float_as_uint(c);
    return ((ull)u << 32) | (ull)u;
}
__device__ __forceinline__ float frcp(float x) {
    float r; asm("rcp.approx.f32 %0,%1;" : "=f"(r) : "f"(x)); return r;
}
__device__ __forceinline__ float fex2(float x) {
    float r; asm("ex2.approx.f32 %0,%1;" : "=f"(r) : "f"(x)); return r;
}

// Branch-free exact-class GELU on a packed fp32x2 pair.
// erf(z) = 1 - (a1 u + ... + a5 u^5) e^{-z^2},  u = 1/(1+p z), z>=0   (A&S 7.1.26, |err|<=1.5e-7)
// gelu(x) = 0.5 x + 0.5|x| (1 - P*E)  with z = |x|/sqrt(2), 0.5|x| = z/sqrt(2).
__device__ __forceinline__ ull gelu2(ull s) {
    const ull C_ISQ2 = pkc(0.70710678118654752f);
    ull a = mul2(s & 0x7FFFFFFF7FFFFFFFULL, C_ISQ2);         // z (both lanes >= 0)
    ull d = fma2(a, pkc(0.3275911f), pkc(1.0f));
    float dl, dh; unpk(d, dl, dh);
    ull u = pk2(frcp(dl), frcp(dh));
    ull p = fma2(u, pkc(1.061405429f), pkc(-1.453152027f));
    p = fma2(u, p, pkc(1.421413741f));
    p = fma2(u, p, pkc(-0.284496736f));
    p = fma2(u, p, pkc(0.254829592f));
    p = mul2(p, u);
    ull m = mul2(mul2(a, a), pkc(-1.4426950408889634f));     // -z^2 * log2(e)
    float ml, mh; unpk(m, ml, mh);
    ull e = pk2(fex2(ml), fex2(mh));
    ull pe = mul2(p, e);
    ull hm = mul2(a, C_ISQ2);                                // 0.5|x|
    ull r = fma2(pe ^ 0x8000000080000000ULL, hm, hm);        // 0.5|x|(1-PE)
    return fma2(s, pkc(0.5f), r);                            // 0.5x + ...
}

__global__ void __launch_bounds__(THREADS, 2) edgeconv_mlp_kernel(
    const float* __restrict__ x,
    const float* __restrict__ W1, const float* __restrict__ g1, const float* __restrict__ b1,
    const float* __restrict__ m1, const float* __restrict__ v1,
    const float* __restrict__ W2, const float* __restrict__ g2, const float* __restrict__ b2,
    const float* __restrict__ m2, const float* __restrict__ v2,
    const float* __restrict__ W3, const float* __restrict__ g3, const float* __restrict__ b3,
    const float* __restrict__ m3, const float* __restrict__ v3,
    float* __restrict__ out)
{
    __shared__ float sm[SM_TOT];
    const int t = threadIdx.x;

    // Fold BN into weights/bias (per block; small, L2-cached)
    for (int i = t; i < 64 * 32; i += THREADS) {
        int o = i >> 5;
        sm[SM_W1 + i] = W1[i] * (g1[o] * rsqrtf(v1[o] + EPS));
    }
    for (int i = t; i < 64 * 64; i += THREADS) {
        int o = i >> 6;
        sm[SM_W2 + i] = W2[i] * (g2[o] * rsqrtf(v2[o] + EPS));
        sm[SM_W3 + i] = W3[i] * (g3[o] * rsqrtf(v3[o] + EPS));
    }
    if (t < 64) {
        sm[SM_B1 + t] = b1[t] - m1[t] * (g1[t] * rsqrtf(v1[t] + EPS));
        sm[SM_B2 + t] = b2[t] - m2[t] * (g2[t] * rsqrtf(v2[t] + EPS));
        sm[SM_B3 + t] = b3[t] - m3[t] * (g3[t] * rsqrtf(v3[t] + EPS));
    }
    __syncthreads();

    const int p = blockIdx.x * THREADS + t;

    // x[p, 0:32] as 16 packed pairs (128B aligned)
    ull xp[16];
    {
        const ulonglong2* xg = (const ulonglong2*)(x + (size_t)p * 32);
        #pragma unroll
        for (int i = 0; i < 8; ++i) { ulonglong2 v = xg[i]; xp[2 * i] = v.x; xp[2 * i + 1] = v.y; }
    }

    // ---- Stage 1: 32 -> 64, outputs paired, results stay packed in registers ----
    ull hp[32];
    const float* bp1 = sm + SM_B1;
    #pragma unroll 2
    for (int o = 0; o < 64; o += 2) {
        const ulonglong2* w0 = (const ulonglong2*)(sm + SM_W1 + o * 32);  // row o; row o+1 = +8
        ull a0 = 0, b0 = 0, a1 = 0, b1v = 0;
        #pragma unroll
        for (int q = 0; q < 8; ++q) {
            ulonglong2 wv0 = w0[q];
            ulonglong2 wv1 = w0[q + 8];
            a0  = fma2(wv0.x, xp[2 * q],     a0);
            b0  = fma2(wv0.y, xp[2 * q + 1], b0);
            a1  = fma2(wv1.x, xp[2 * q],     a1);
            b1v = fma2(wv1.y, xp[2 * q + 1], b1v);
        }
        float r0 = sum2(add2(a0, b0))  + bp1[o];
        float r1 = sum2(add2(a1, b1v)) + bp1[o + 1];
        hp[o >> 1] = gelu2(pk2(r0, r1));
    }

    // ---- Stage 2: 64 -> 64 ----
    ull hq[32];
    const float* bp2 = sm + SM_B2;
    #pragma unroll 2
    for (int o = 0; o < 64; o += 2) {
        const ulonglong2* w0 = (const ulonglong2*)(sm + SM_W2 + o * 64);  // row o; row o+1 = +16
        ull a0 = 0, b0 = 0, a1 = 0, b1v = 0;
        #pragma unroll
        for (int q = 0; q < 16; ++q) {
            ulonglong2 wv0 = w0[q];
            ulonglong2 wv1 = w0[q + 16];
            a0  = fma2(wv0.x, hp[2 * q],     a0);
            b0  = fma2(wv0.y, hp[2 * q + 1], b0);
            a1  = fma2(wv1.x, hp[2 * q],     a1);
            b1v = fma2(wv1.y, hp[2 * q + 1], b1v);
        }
        float r0 = sum2(add2(a0, b0))  + bp2[o];
        float r1 = sum2(add2(a1, b1v)) + bp2[o + 1];
        hq[o >> 1] = gelu2(pk2(r0, r1));
    }

    // ---- Stage 3: 64 -> 64, store transposed out[b, o, n] (n contiguous per warp) ----
    const float* bp3 = sm + SM_B3;
    float* outp = out + (size_t)(p >> 10) * 65536 + (p & 1023);
    #pragma unroll 2
    for (int o = 0; o < 64; o += 2) {
        const ulonglong2* w0 = (const ulonglong2*)(sm + SM_W3 + o * 64);
        ull a0 = 0, b0 = 0, a1 = 0, b1v = 0;
        #pragma unroll
        for (int q = 0; q < 16; ++q) {
            ulonglong2 wv0 = w0[q];
            ulonglong2 wv1 = w0[q + 16];
            a0  = fma2(wv0.x, hq[2 * q],     a0);
            b0  = fma2(wv0.y, hq[2 * q + 1], b0);
            a1  = fma2(wv1.x, hq[2 * q],     a1);
            b1v = fma2(wv1.y, hq[2 * q + 1], b1v);
        }
        float r0 = sum2(add2(a0, b0))  + bp3[o];
        float r1 = sum2(add2(a1, b1v)) + bp3[o + 1];
        ull g = gelu2(pk2(r0, r1));
        float glo, ghi; unpk(g, glo, ghi);
        outp[(size_t)o * 1024]       = glo;
        outp[(size_t)(o + 1) * 1024] = ghi;
    }
}

extern "C" void kernel_launch(void* const* d_in, const int* in_sizes, int n_in,
                              void* d_out, int out_size)
{
    const float* x  = (const float*)d_in[0];
    const float* W1 = (const float*)d_in[1];
    const float* g1 = (const float*)d_in[2];
    const float* b1 = (const float*)d_in[3];
    const float* m1 = (const float*)d_in[4];
    const float* v1 = (const float*)d_in[5];
    const float* W2 = (const float*)d_in[6];
    const float* g2 = (const float*)d_in[7];
    const float* b2 = (const float*)d_in[8];
    const float* m2 = (const float*)d_in[9];
    const float* v2 = (const float*)d_in[10];
    const float* W3 = (const float*)d_in[11];
    const float* g3 = (const float*)d_in[12];
    const float* b3 = (const float*)d_in[13];
    const float* m3 = (const float*)d_in[14];
    const float* v3 = (const float*)d_in[15];
    float* out = (float*)d_out;

    edgeconv_mlp_kernel<<<NPTS / THREADS, THREADS>>>(
        x, W1, g1, b1, m1, v1, W2, g2, b2, m2, v2, W3, g3, b3, m3, v3, out);
}